// round 13
// baseline (speedup 1.0000x reference)
#include <cuda_runtime.h>
#include <cuda_fp16.h>
#include <cstdint>

#define BATCH 8
#define SEQ   2048
#define DIM   512
#define BM    64
#define BN    128
#define STEPS 24           // per tile: 16 K chunks (32-depth) + 8 V chunks (16-key)

// f16 scratch; K/V stored PERMUTED (unmasked keys first). Q pre-scaled.
__device__ __half g_Qh[(size_t)BATCH*SEQ*DIM];
__device__ __half g_Kh[(size_t)BATCH*SEQ*DIM];
__device__ __half g_Vh[(size_t)BATCH*SEQ*DIM];
__device__ int    g_pos[BATCH*SEQ];
__device__ int    g_cnt[BATCH];

// ---- smem layout (bytes), per CTA (2 CTAs/SM) ----
// Q: 64 x 512 f16, row stride 1040
// ring: 3 slots x 10240; K chunk = 128 keys x 32 depth (stride 80),
//                        V chunk = 16 keys x 256 dims (stride 528)
// P: 64 rows x 128 keys f16, stride 272
// ssum aliases the ring (ring idle during epilogue)
constexpr int SLOT    = 10240;
constexpr int OFF_Q   = 0;        // 66560
constexpr int OFF_RING= 66560;    // + 30720
constexpr int OFF_P   = 97280;    // + 17408
constexpr int SMEM_TOTAL = 114688;

__device__ __forceinline__ uint32_t smem_u32(const void* p) {
    uint32_t a;
    asm("{ .reg .u64 t; cvta.to.shared.u64 t, %1; cvt.u32.u64 %0, t; }" : "=r"(a) : "l"(p));
    return a;
}
__device__ __forceinline__ void cpa16(uint32_t dst, const void* src) {
    asm volatile("cp.async.cg.shared.global [%0], [%1], 16;" :: "r"(dst), "l"(src));
}
__device__ __forceinline__ void cpa_commit() { asm volatile("cp.async.commit_group;" ::: "memory"); }
__device__ __forceinline__ void cpa_wait1()  { asm volatile("cp.async.wait_group 1;" ::: "memory"); }
__device__ __forceinline__ void cpa_wait0()  { asm volatile("cp.async.wait_group 0;" ::: "memory"); }

__device__ __forceinline__ void ldsm4(uint32_t* r, uint32_t a) {
    asm volatile("ldmatrix.sync.aligned.m8n8.x4.shared.b16 {%0,%1,%2,%3}, [%4];"
        : "=r"(r[0]), "=r"(r[1]), "=r"(r[2]), "=r"(r[3]) : "r"(a));
}
__device__ __forceinline__ void ldsm4t(uint32_t* r, uint32_t a) {
    asm volatile("ldmatrix.sync.aligned.m8n8.x4.trans.shared.b16 {%0,%1,%2,%3}, [%4];"
        : "=r"(r[0]), "=r"(r[1]), "=r"(r[2]), "=r"(r[3]) : "r"(a));
}
__device__ __forceinline__ void mma16816(float* c, const uint32_t* a, uint32_t b0, uint32_t b1) {
    asm volatile("mma.sync.aligned.m16n8k16.row.col.f32.f16.f16.f32 "
        "{%0,%1,%2,%3}, {%4,%5,%6,%7}, {%8,%9}, {%0,%1,%2,%3};"
        : "+f"(c[0]), "+f"(c[1]), "+f"(c[2]), "+f"(c[3])
        : "r"(a[0]), "r"(a[1]), "r"(a[2]), "r"(a[3]), "r"(b0), "r"(b1));
}
__device__ __forceinline__ uint32_t packh(float f0, float f1) {
    uint32_t r;
    asm("cvt.rn.f16x2.f32 %0, %1, %2;" : "=r"(r) : "f"(f1), "f"(f0));
    return r;
}
__device__ __forceinline__ float ex2(float x) {
    float y;
    asm("ex2.approx.ftz.f32 %0, %1;" : "=f"(y) : "f"(x));
    return y;
}

// ---- prepass 1: Q f32 -> f16, scaled by log2(e)/sqrt(512) ----
__global__ void prep_q(const float* __restrict__ Q) {
    size_t i4 = ((size_t)blockIdx.x * blockDim.x + threadIdx.x) * 4;
    if (i4 >= (size_t)BATCH * SEQ * DIM) return;
    const float sc = 0.06376781387566735f;
    float4 f = *(const float4*)(Q + i4);
    uint2 u;
    u.x = packh(f.x * sc, f.y * sc);
    u.y = packh(f.z * sc, f.w * sc);
    *(uint2*)(g_Qh + i4) = u;
}

// ---- prepass 2: stable partition permutation via block scan (1 block/batch) ----
__global__ void scan_mask(const int* __restrict__ mask) {
    __shared__ int s0[SEQ], s1[SEQ];
    const int b = blockIdx.x;
    const int* mb = mask + b * SEQ;
    int* cur = s0;
    int* nxt = s1;
    for (int k = threadIdx.x; k < SEQ; k += 1024)
        cur[k] = (mb[k] == 0) ? 1 : 0;
    __syncthreads();
    for (int off = 1; off < SEQ; off <<= 1) {
        for (int k = threadIdx.x; k < SEQ; k += 1024) {
            int v = cur[k];
            if (k >= off) v += cur[k - off];
            nxt[k] = v;
        }
        __syncthreads();
        int* tmp = cur; cur = nxt; nxt = tmp;
    }
    const int total = cur[SEQ - 1];
    for (int k = threadIdx.x; k < SEQ; k += 1024) {
        int U = cur[k];
        g_pos[b * SEQ + k] = (mb[k] == 0) ? (U - 1) : (total + k - U);
    }
    if (threadIdx.x == 0) g_cnt[b] = total;
}

// ---- prepass 3: gather-convert K/V into permuted f16 arrays ----
__global__ void gather_kv(const float* __restrict__ K, const float* __restrict__ V) {
    const int wid = threadIdx.x >> 5, lane = threadIdx.x & 31;
    const int k = blockIdx.x * 8 + wid;
    const int b = blockIdx.y;
    const int j = g_pos[b * SEQ + k];
    const float* ksrc = K + ((size_t)b * SEQ + k) * DIM;
    const float* vsrc = V + ((size_t)b * SEQ + k) * DIM;
    __half* kd = g_Kh + ((size_t)b * SEQ + j) * DIM;
    __half* vd = g_Vh + ((size_t)b * SEQ + j) * DIM;
    #pragma unroll
    for (int i = 0; i < 4; i++) {
        int o = lane * 4 + i * 128;
        float4 f = *(const float4*)(ksrc + o);
        uint2 u;
        u.x = packh(f.x, f.y); u.y = packh(f.z, f.w);
        *(uint2*)(kd + o) = u;
        f = *(const float4*)(vsrc + o);
        u.x = packh(f.x, f.y); u.y = packh(f.z, f.w);
        *(uint2*)(vd + o) = u;
    }
}

// ---- main kernel: BM=64, BN=128, 256 threads, 2 CTAs/SM ----
__global__ __launch_bounds__(256, 2)
void attn_v9(float* __restrict__ out)
{
    extern __shared__ char smem[];
    const uint32_t sbase = smem_u32(smem);
    uint32_t* sP32 = (uint32_t*)(smem + OFF_P);
    float* ssum = (float*)(smem + OFF_RING);   // aliases ring (epilogue only)

    const int tid  = threadIdx.x;
    const int wid  = tid >> 5;
    const int lane = tid & 31;
    const int gid  = lane >> 2;
    const int tig  = lane & 3;
    const int mi   = wid & 1;    // query rows mi*32..+31
    const int ng   = wid >> 1;   // QK: keys ng*32..+31 ; PV: dims ng*64..+63

    const int b  = blockIdx.y;
    const int q0 = blockIdx.x * BM;
    const int vh = blockIdx.z;   // DV half (256 dims)

    const int cnt = g_cnt[b];
    const int nt  = (cnt + BN - 1) >> 7;
    const int TOTR = nt * STEPS;

    const __half* Qh = g_Qh + ((size_t)b * SEQ + q0) * DIM;
    const __half* Kh = g_Kh + (size_t)b * SEQ * DIM;
    const __half* Vh = g_Vh + (size_t)b * SEQ * DIM + vh * 256;

    // stream item g: tile g/24; s = g%24: s<16 -> K chunk (128 keys x 32 depth),
    // s>=16 -> V chunk (16 keys x 256 dims). slot = g%3.
    auto issue_chunk = [&](int g) {
        int tt = g / STEPS;
        int s  = g - tt * STEPS;
        uint32_t dst = sbase + OFF_RING + (uint32_t)((g % 3) * SLOT);
        if (s < 16) {
            const __half* src = Kh + (size_t)(tt * BN) * DIM + s * 32;
            #pragma unroll
            for (int i = 0; i < 2; i++) {         // 512 cps: 128 rows x 4
                int g2 = tid + i * 256;
                int row = g2 >> 2, j = g2 & 3;
                cpa16(dst + row * 80 + j * 16, src + row * DIM + j * 8);
            }
        } else {
            const __half* src = Vh + (size_t)(tt * BN + (s - 16) * 16) * DIM;
            #pragma unroll
            for (int i = 0; i < 2; i++) {         // 512 cps: 16 rows x 32
                int g2 = tid + i * 256;
                int row = g2 >> 5, j = g2 & 31;
                cpa16(dst + row * 528 + j * 16, src + row * DIM + j * 8);
            }
        }
        cpa_commit();
    };

    // ---- prologue: Q tile (+item 0 same group), item 1 ----
    #pragma unroll
    for (int i = 0; i < 16; i++) {
        int g = tid + i * 256;                    // 4096 cps: 64 rows x 64
        int row = g >> 6, j = g & 63;
        cpa16(sbase + OFF_Q + row * 1040 + j * 16, Qh + row * DIM + j * 8);
    }
    {   // item 0 = K chunk (t0, s0)
        #pragma unroll
        for (int i = 0; i < 2; i++) {
            int g2 = tid + i * 256;
            int row = g2 >> 2, j = g2 & 3;
            cpa16(sbase + OFF_RING + row * 80 + j * 16, Kh + row * DIM + j * 8);
        }
        cpa_commit();
    }
    issue_chunk(1);

    // ldmatrix bases (bytes)
    const uint32_t aQ0 = sbase + OFF_Q + (uint32_t)((mi * 32 + (lane & 15)) * 1040) + (lane >> 4) * 16;
    const uint32_t aQ1 = aQ0 + 16 * 1040;
    const uint32_t bK  = (uint32_t)((ng * 32 + (lane & 7) + ((lane >> 4) & 1) * 8) * 80)
                       + ((lane >> 3) & 1) * 16;
    const uint32_t aP0 = sbase + OFF_P + (uint32_t)((mi * 32 + (lane & 15)) * 272) + (lane >> 4) * 16;
    const uint32_t aP1 = aP0 + 16 * 272;
    const uint32_t bV  = (uint32_t)(((lane & 7) + ((lane >> 3) & 1) * 8) * 528)
                       + (uint32_t)((ng * 64 + (lane >> 4) * 8) * 2);

    float ll[4] = {0.f, 0.f, 0.f, 0.f};
    float O[2][8][4];
    #pragma unroll
    for (int m = 0; m < 2; m++)
        #pragma unroll
        for (int n = 0; n < 8; n++)
            #pragma unroll
            for (int r = 0; r < 4; r++) O[m][n][r] = 0.f;

    for (int t = 0; t < nt; t++) {
        float S[2][4][4];
        #pragma unroll
        for (int m = 0; m < 2; m++)
            #pragma unroll
            for (int n = 0; n < 4; n++)
                #pragma unroll
                for (int r = 0; r < 4; r++) S[m][n][r] = 0.f;

        // ======== QK^T over 16 depth-chunks of 32 ========
        #pragma unroll
        for (int c = 0; c < 16; c++) {
            const int g = t * STEPS + c;
            cpa_wait1();
            __syncthreads();
            if (g + 2 < TOTR) issue_chunk(g + 2);

            const uint32_t kslot = sbase + OFF_RING + (uint32_t)((g % 3) * SLOT);
            #pragma unroll
            for (int ks = 0; ks < 2; ks++) {
                uint32_t a0[4], a1[4], b0[4], b1[4];
                uint32_t qoff = (uint32_t)((c * 32 + ks * 16) * 2);
                ldsm4(a0, aQ0 + qoff);
                ldsm4(a1, aQ1 + qoff);
                ldsm4(b0, kslot + bK + ks * 32);
                ldsm4(b1, kslot + bK + 16 * 80 + ks * 32);
                mma16816(S[0][0], a0, b0[0], b0[1]);
                mma16816(S[0][1], a0, b0[2], b0[3]);
                mma16816(S[0][2], a0, b1[0], b1[1]);
                mma16816(S[0][3], a0, b1[2], b1[3]);
                mma16816(S[1][0], a1, b0[0], b0[1]);
                mma16816(S[1][1], a1, b0[2], b0[3]);
                mma16816(S[1][2], a1, b1[0], b1[1]);
                mma16816(S[1][3], a1, b1[2], b1[3]);
            }
        }

        // ======== softmax: bias = -inf for padding keys (idx >= cnt) ========
        const int kbase = t * BN + ng * 32 + 2 * tig;
        #pragma unroll
        for (int f = 0; f < 4; f++) {
            float ba = (kbase + f * 8)     < cnt ? 0.f : -1e30f;
            float bb = (kbase + f * 8 + 1) < cnt ? 0.f : -1e30f;
            #pragma unroll
            for (int mt = 0; mt < 2; mt++) {
                float p0 = ex2(S[mt][f][0] + ba);
                float p1 = ex2(S[mt][f][1] + bb);
                float p2 = ex2(S[mt][f][2] + ba);
                float p3 = ex2(S[mt][f][3] + bb);
                ll[mt * 2 + 0] += p0 + p1;
                ll[mt * 2 + 1] += p2 + p3;
                int r0 = mi * 32 + mt * 16 + gid;
                sP32[r0 * 68 + ng * 16 + f * 4 + tig] = packh(p0, p1);
                sP32[(r0 + 8) * 68 + ng * 16 + f * 4 + tig] = packh(p2, p3);
            }
        }

        // ======== P @ V over 8 16-key V chunks ========
        #pragma unroll
        for (int q = 0; q < 8; q++) {
            const int g = t * STEPS + 16 + q;
            if (g + 1 < TOTR) cpa_wait1(); else cpa_wait0();
            __syncthreads();   // V(q) ready; P fully visible (q==0)
            if (g + 2 < TOTR) issue_chunk(g + 2);

            const uint32_t vslot = sbase + OFF_RING + (uint32_t)((g % 3) * SLOT);
            uint32_t pa0[4], pa1[4];
            uint32_t poff = (uint32_t)(q * 32);
            ldsm4(pa0, aP0 + poff);
            ldsm4(pa1, aP1 + poff);
            #pragma unroll
            for (int nt2 = 0; nt2 < 4; nt2++) {
                uint32_t vb[4];
                ldsm4t(vb, vslot + bV + nt2 * 32);
                mma16816(O[0][nt2 * 2],     pa0, vb[0], vb[1]);
                mma16816(O[0][nt2 * 2 + 1], pa0, vb[2], vb[3]);
                mma16816(O[1][nt2 * 2],     pa1, vb[0], vb[1]);
                mma16816(O[1][nt2 * 2 + 1], pa1, vb[2], vb[3]);
            }
        }
    }

    // ======== epilogue (ssum aliases ring; ring is done) ========
    #pragma unroll
    for (int i = 0; i < 4; i++) {
        ll[i] += __shfl_xor_sync(0xffffffffu, ll[i], 1);
        ll[i] += __shfl_xor_sync(0xffffffffu, ll[i], 2);
    }
    __syncthreads();
    if (tig == 0) {
        #pragma unroll
        for (int mt = 0; mt < 2; mt++)
            #pragma unroll
            for (int rh = 0; rh < 2; rh++)
                ssum[ng * 64 + mi * 32 + mt * 16 + rh * 8 + gid] = ll[mt * 2 + rh];
    }
    __syncthreads();

    #pragma unroll
    for (int mt = 0; mt < 2; mt++) {
        #pragma unroll
        for (int rh = 0; rh < 2; rh++) {
            int row = mi * 32 + mt * 16 + rh * 8 + gid;
            float l = ssum[row] + ssum[64 + row] + ssum[128 + row] + ssum[192 + row];
            float inv = 1.0f / l;
            float* orow = out + ((size_t)b * SEQ + q0 + row) * DIM + vh * 256 + ng * 64 + 2 * tig;
            #pragma unroll
            for (int j = 0; j < 8; j++) {
                float2 v;
                v.x = O[mt][j][rh * 2]     * inv;
                v.y = O[mt][j][rh * 2 + 1] * inv;
                *(float2*)(orow + j * 8) = v;
            }
        }
    }
}

extern "C" void kernel_launch(void* const* d_in, const int* in_sizes, int n_in,
                              void* d_out, int out_size) {
    const float* Q = (const float*)d_in[0];
    const float* K = (const float*)d_in[1];
    const float* V = (const float*)d_in[2];
    const int* mask = (const int*)d_in[3];
    float* out = (float*)d_out;

    size_t n4 = (size_t)BATCH * SEQ * DIM / 4;
    prep_q<<<(unsigned)((n4 + 255) / 256), 256>>>(Q);
    scan_mask<<<BATCH, 1024>>>(mask);
    gather_kv<<<dim3(SEQ / 8, BATCH), 256>>>(K, V);

    cudaFuncSetAttribute(attn_v9, cudaFuncAttributeMaxDynamicSharedMemorySize, SMEM_TOTAL);
    dim3 grid(SEQ / BM, BATCH, 2);
    attn_v9<<<grid, 256, SMEM_TOTAL>>>(out);
}

// round 14
// speedup vs baseline: 1.2562x; 1.2562x over previous
#include <cuda_runtime.h>
#include <cuda_fp16.h>
#include <cstdint>

#define BATCH 8
#define SEQ   2048
#define DIM   512
#define BM    128
#define BN    128
#define STEPS 24           // per tile: 16 K chunks (32-depth) + 8 V chunks (16-key)

// f16 scratch; K/V stored PERMUTED (unmasked keys first). Q pre-scaled.
__device__ __half g_Qh[(size_t)BATCH*SEQ*DIM];
__device__ __half g_Kh[(size_t)BATCH*SEQ*DIM];
__device__ __half g_Vh[(size_t)BATCH*SEQ*DIM];
__device__ int    g_pos[BATCH*SEQ];
__device__ int    g_cnt[BATCH];

// ---- smem layout (bytes) ----
// Q: 128 x 512 f16, stride 1040 (read by mi-groups)
// K ring: 3 x 10240; chunk = 128 keys x 32 depth, stride 80 (group ng owns rows ng*32..+31)
// V ring: 3 x 8448;  chunk = 16 keys x 256 dims, stride 528 (group ng owns cols ng*64..+63)
// P: 128 x 128 f16, stride 272 (partitioned by mi)
constexpr int KSLOT  = 10240;
constexpr int VSLOT  = 8448;
constexpr int OFF_Q   = 0;         // 133120
constexpr int OFF_KR  = 133120;    // + 30720
constexpr int OFF_VR  = 163840;    // + 25344
constexpr int OFF_P   = 189184;    // + 34816
constexpr int OFF_SUM = 224000;    // + 2048
constexpr int SMEM_TOTAL = 226048;

__device__ __forceinline__ uint32_t smem_u32(const void* p) {
    uint32_t a;
    asm("{ .reg .u64 t; cvta.to.shared.u64 t, %1; cvt.u32.u64 %0, t; }" : "=r"(a) : "l"(p));
    return a;
}
__device__ __forceinline__ void cpa16(uint32_t dst, const void* src) {
    asm volatile("cp.async.cg.shared.global [%0], [%1], 16;" :: "r"(dst), "l"(src));
}
__device__ __forceinline__ void cpa_commit() { asm volatile("cp.async.commit_group;" ::: "memory"); }
__device__ __forceinline__ void cpa_wait1()  { asm volatile("cp.async.wait_group 1;" ::: "memory"); }
__device__ __forceinline__ void cpa_wait0()  { asm volatile("cp.async.wait_group 0;" ::: "memory"); }
__device__ __forceinline__ void barg(int id) {
    asm volatile("bar.sync %0, 128;" :: "r"(id) : "memory");
}

__device__ __forceinline__ void ldsm4(uint32_t* r, uint32_t a) {
    asm volatile("ldmatrix.sync.aligned.m8n8.x4.shared.b16 {%0,%1,%2,%3}, [%4];"
        : "=r"(r[0]), "=r"(r[1]), "=r"(r[2]), "=r"(r[3]) : "r"(a));
}
__device__ __forceinline__ void ldsm4t(uint32_t* r, uint32_t a) {
    asm volatile("ldmatrix.sync.aligned.m8n8.x4.trans.shared.b16 {%0,%1,%2,%3}, [%4];"
        : "=r"(r[0]), "=r"(r[1]), "=r"(r[2]), "=r"(r[3]) : "r"(a));
}
__device__ __forceinline__ void mma16816(float* c, const uint32_t* a, uint32_t b0, uint32_t b1) {
    asm volatile("mma.sync.aligned.m16n8k16.row.col.f32.f16.f16.f32 "
        "{%0,%1,%2,%3}, {%4,%5,%6,%7}, {%8,%9}, {%0,%1,%2,%3};"
        : "+f"(c[0]), "+f"(c[1]), "+f"(c[2]), "+f"(c[3])
        : "r"(a[0]), "r"(a[1]), "r"(a[2]), "r"(a[3]), "r"(b0), "r"(b1));
}
__device__ __forceinline__ uint32_t packh(float f0, float f1) {
    uint32_t r;
    asm("cvt.rn.f16x2.f32 %0, %1, %2;" : "=r"(r) : "f"(f1), "f"(f0));
    return r;
}
__device__ __forceinline__ float ex2(float x) {
    float y;
    asm("ex2.approx.ftz.f32 %0, %1;" : "=f"(y) : "f"(x));
    return y;
}

// ---- prepass 1: Q f32 -> f16, scaled by log2(e)/sqrt(512) ----
__global__ void prep_q(const float* __restrict__ Q) {
    size_t i4 = ((size_t)blockIdx.x * blockDim.x + threadIdx.x) * 4;
    if (i4 >= (size_t)BATCH * SEQ * DIM) return;
    const float sc = 0.06376781387566735f;
    float4 f = *(const float4*)(Q + i4);
    uint2 u;
    u.x = packh(f.x * sc, f.y * sc);
    u.y = packh(f.z * sc, f.w * sc);
    *(uint2*)(g_Qh + i4) = u;
}

// ---- prepass 2: stable partition permutation via block scan ----
__global__ void scan_mask(const int* __restrict__ mask) {
    __shared__ int s0[SEQ], s1[SEQ];
    const int b = blockIdx.x;
    const int* mb = mask + b * SEQ;
    int* cur = s0;
    int* nxt = s1;
    for (int k = threadIdx.x; k < SEQ; k += 1024)
        cur[k] = (mb[k] == 0) ? 1 : 0;
    __syncthreads();
    for (int off = 1; off < SEQ; off <<= 1) {
        for (int k = threadIdx.x; k < SEQ; k += 1024) {
            int v = cur[k];
            if (k >= off) v += cur[k - off];
            nxt[k] = v;
        }
        __syncthreads();
        int* tmp = cur; cur = nxt; nxt = tmp;
    }
    const int total = cur[SEQ - 1];
    for (int k = threadIdx.x; k < SEQ; k += 1024) {
        int U = cur[k];
        g_pos[b * SEQ + k] = (mb[k] == 0) ? (U - 1) : (total + k - U);
    }
    if (threadIdx.x == 0) g_cnt[b] = total;
}

// ---- prepass 3: gather only UNMASKED keys (tail stays zero = deterministic) ----
__global__ void gather_kv(const float* __restrict__ K, const float* __restrict__ V,
                          const int* __restrict__ mask) {
    const int wid = threadIdx.x >> 5, lane = threadIdx.x & 31;
    const int k = blockIdx.x * 8 + wid;
    const int b = blockIdx.y;
    if (mask[b * SEQ + k] != 0) return;
    const int j = g_pos[b * SEQ + k];
    const float* ksrc = K + ((size_t)b * SEQ + k) * DIM;
    const float* vsrc = V + ((size_t)b * SEQ + k) * DIM;
    __half* kd = g_Kh + ((size_t)b * SEQ + j) * DIM;
    __half* vd = g_Vh + ((size_t)b * SEQ + j) * DIM;
    #pragma unroll
    for (int i = 0; i < 4; i++) {
        int o = lane * 4 + i * 128;
        float4 f = *(const float4*)(ksrc + o);
        uint2 u;
        u.x = packh(f.x, f.y); u.y = packh(f.z, f.w);
        *(uint2*)(kd + o) = u;
        f = *(const float4*)(vsrc + o);
        u.x = packh(f.x, f.y); u.y = packh(f.z, f.w);
        *(uint2*)(vd + o) = u;
    }
}

// ---- main kernel: v8 tiling, group-scoped sync ----
__global__ __launch_bounds__(512, 1)
void attn_v10(float* __restrict__ out)
{
    extern __shared__ char smem[];
    const uint32_t sbase = smem_u32(smem);
    uint32_t* sP32 = (uint32_t*)(smem + OFF_P);
    float* ssum = (float*)(smem + OFF_SUM);

    const int tid  = threadIdx.x;
    const int wid  = tid >> 5;
    const int lane = tid & 31;
    const int gid  = lane >> 2;
    const int tig  = lane & 3;
    const int mi   = wid & 3;    // query rows mi*32..+31 (Q/P group)
    const int ng   = wid >> 2;   // K rows ng*32 / V cols ng*64 (K/V group)
    const int gtid = tid & 127;                      // index within ng-group
    const int gqid = (wid >> 2) * 32 + lane;         // index within mi-group

    const int b  = blockIdx.y;
    const int q0 = blockIdx.x * BM;
    const int vh = blockIdx.z;

    const int cnt = g_cnt[b];
    const int nt  = (cnt + BN - 1) >> 7;
    const int TOT = nt * STEPS;

    const __half* Qh = g_Qh + ((size_t)b * SEQ + q0) * DIM;
    const __half* Kh = g_Kh + (size_t)b * SEQ * DIM;
    const __half* Vh = g_Vh + (size_t)b * SEQ * DIM + vh * 256;

    // group-sliced chunk copy. K chunk (tile tt, depth s*32): group copies rows ng*32..+31.
    auto issueK = [&](int tt, int s) {
        int gk = tt * 16 + s;
        uint32_t dst = sbase + OFF_KR + (uint32_t)((gk % 3) * KSLOT);
        const __half* src = Kh + (size_t)(tt * BN + ng * 32) * DIM + s * 32;
        #pragma unroll
        for (int i = 0; i < 2; i++) {      // 32 rows x 2 cps (32 f16 = 2x16B)
            int c = gtid + i * 128;
            int row = c >> 3, j = c & 7;   // j<4 real? 32 f16 = 64B = 4 cps/row
            // 32 rows x 4 cps = 128 -> 1 per thread... use single pass below
            (void)row; (void)j;
        }
        // 32 rows x 4 cps/row = 128 cps, 1 per thread
        {
            int row = gtid >> 2, j = gtid & 3;
            cpa16(dst + (uint32_t)((ng * 32 + row) * 80 + j * 16),
                  src + row * DIM + j * 8);
        }
        cpa_commit();
    };
    // V chunk (tile tt, keys s*16): group copies cols ng*64..+63 (128B/row)
    auto issueV = [&](int tt, int s) {
        int gv = tt * 8 + s;
        uint32_t dst = sbase + OFF_VR + (uint32_t)((gv % 3) * VSLOT);
        const __half* src = Vh + (size_t)(tt * BN + s * 16) * DIM + ng * 64;
        int row = gtid >> 3, j = gtid & 7;  // 16 rows x 8 cps = 128
        cpa16(dst + (uint32_t)(row * 528 + ng * 128 + j * 16),
              src + row * DIM + j * 8);
        cpa_commit();
    };

    // ---- prologue: Q (mi slice) + K chunk 0 in one group; K chunk 1 ----
    #pragma unroll
    for (int i = 0; i < 16; i++) {          // mi-group: 32 rows x 64 cps = 2048, 16/thread
        int c = gqid + i * 128;
        int row = c >> 6, j = c & 63;
        cpa16(sbase + OFF_Q + (uint32_t)((mi * 32 + row) * 1040 + j * 16),
              Qh + (mi * 32 + row) * DIM + j * 8);
    }
    {   // K chunk (0,0) inline, same commit group as Q
        int row = gtid >> 2, j = gtid & 3;
        cpa16(sbase + OFF_KR + (uint32_t)((ng * 32 + row) * 80 + j * 16),
              Kh + (size_t)(ng * 32 + row) * DIM + j * 8);
        cpa_commit();
    }
    issueK(0, 1);
    cpa_wait1();       // Q + K0 arrived (mine)
    barg(5 + mi);      // Q visible within mi-group
    barg(1 + ng);      // K0 visible within ng-group

    // ldmatrix bases (bytes)
    const uint32_t aQ0 = sbase + OFF_Q + (uint32_t)((mi * 32 + (lane & 15)) * 1040) + (lane >> 4) * 16;
    const uint32_t aQ1 = aQ0 + 16 * 1040;
    const uint32_t bK  = (uint32_t)((ng * 32 + (lane & 7) + ((lane >> 4) & 1) * 8) * 80)
                       + ((lane >> 3) & 1) * 16;
    const uint32_t aP0 = sbase + OFF_P + (uint32_t)((mi * 32 + (lane & 15)) * 272) + (lane >> 4) * 16;
    const uint32_t aP1 = aP0 + 16 * 272;
    const uint32_t bV  = (uint32_t)(((lane & 7) + ((lane >> 3) & 1) * 8) * 528)
                       + (uint32_t)((ng * 64 + (lane >> 4) * 8) * 2);

    float ll[4] = {0.f, 0.f, 0.f, 0.f};
    float O[2][8][4];
    #pragma unroll
    for (int m = 0; m < 2; m++)
        #pragma unroll
        for (int n = 0; n < 8; n++)
            #pragma unroll
            for (int r = 0; r < 4; r++) O[m][n][r] = 0.f;

    for (int t = 0; t < nt; t++) {
        float S[2][4][4];
        #pragma unroll
        for (int m = 0; m < 2; m++)
            #pragma unroll
            for (int n = 0; n < 4; n++)
                #pragma unroll
                for (int r = 0; r < 4; r++) S[m][n][r] = 0.f;

        // ======== QK^T over 16 depth-chunks of 32 (chunk c data already awaited) ========
        #pragma unroll 4
        for (int c = 0; c < 16; c++) {
            const int u = t * STEPS + c;
            // issue chunk u+2
            if (c + 2 < 16) issueK(t, c + 2);
            else issueV(t, c + 2 - 16);

            const uint32_t kslot = sbase + OFF_KR + (uint32_t)(((t * 16 + c) % 3) * KSLOT);
            #pragma unroll
            for (int ks = 0; ks < 2; ks++) {
                uint32_t a0[4], a1[4], b0[4], b1[4];
                uint32_t qoff = (uint32_t)((c * 32 + ks * 16) * 2);
                ldsm4(a0, aQ0 + qoff);
                ldsm4(a1, aQ1 + qoff);
                ldsm4(b0, kslot + bK + ks * 32);
                ldsm4(b1, kslot + bK + 16 * 80 + ks * 32);
                mma16816(S[0][0], a0, b0[0], b0[1]);
                mma16816(S[0][1], a0, b0[2], b0[3]);
                mma16816(S[0][2], a0, b1[0], b1[1]);
                mma16816(S[0][3], a0, b1[2], b1[3]);
                mma16816(S[1][0], a1, b0[0], b0[1]);
                mma16816(S[1][1], a1, b0[2], b0[3]);
                mma16816(S[1][2], a1, b1[0], b1[1]);
                mma16816(S[1][3], a1, b1[2], b1[3]);
            }
            // ready chunk u+1 for next iteration (always exists: V chunks follow)
            (void)u;
            cpa_wait1();
            barg(1 + ng);
        }

        // ======== softmax (static max; exp2) ========
        const int kbase = t * BN + ng * 32 + 2 * tig;
        float P0[2][4], P1[2][4], P2[2][4], P3[2][4];
        #pragma unroll
        for (int f = 0; f < 4; f++) {
            float ba = (kbase + f * 8)     < cnt ? 0.f : -1e30f;
            float bb = (kbase + f * 8 + 1) < cnt ? 0.f : -1e30f;
            #pragma unroll
            for (int mt = 0; mt < 2; mt++) {
                P0[mt][f] = ex2(S[mt][f][0] + ba);
                P1[mt][f] = ex2(S[mt][f][1] + bb);
                P2[mt][f] = ex2(S[mt][f][2] + ba);
                P3[mt][f] = ex2(S[mt][f][3] + bb);
                ll[mt * 2 + 0] += P0[mt][f] + P1[mt][f];
                ll[mt * 2 + 1] += P2[mt][f] + P3[mt][f];
            }
        }
        barg(5 + mi);   // mi-peers finished reading P(t-1)
        #pragma unroll
        for (int f = 0; f < 4; f++) {
            #pragma unroll
            for (int mt = 0; mt < 2; mt++) {
                int r0 = mi * 32 + mt * 16 + gid;
                sP32[r0 * 68 + ng * 16 + f * 4 + tig]       = packh(P0[mt][f], P1[mt][f]);
                sP32[(r0 + 8) * 68 + ng * 16 + f * 4 + tig] = packh(P2[mt][f], P3[mt][f]);
            }
        }
        barg(5 + mi);   // P visible within mi-group

        // ======== P @ V over 8 16-key V chunks ========
        #pragma unroll 4
        for (int q = 0; q < 8; q++) {
            const int u = t * STEPS + 16 + q;
            if (q + 2 < 8) issueV(t, q + 2);
            else if (t + 1 < nt) issueK(t + 1, q - 6);

            const uint32_t vslot = sbase + OFF_VR + (uint32_t)(((t * 8 + q) % 3) * VSLOT);
            uint32_t pa0[4], pa1[4];
            ldsm4(pa0, aP0 + (uint32_t)(q * 32));
            ldsm4(pa1, aP1 + (uint32_t)(q * 32));
            #pragma unroll
            for (int nt2 = 0; nt2 < 4; nt2++) {
                uint32_t vb[4];
                ldsm4t(vb, vslot + bV + nt2 * 32);
                mma16816(O[0][nt2 * 2],     pa0, vb[0], vb[1]);
                mma16816(O[0][nt2 * 2 + 1], pa0, vb[2], vb[3]);
                mma16816(O[1][nt2 * 2],     pa1, vb[0], vb[1]);
                mma16816(O[1][nt2 * 2 + 1], pa1, vb[2], vb[3]);
            }
            if (u + 1 < TOT) {
                cpa_wait1();
                barg(1 + ng);
            }
        }
    }

    // ======== epilogue ========
    #pragma unroll
    for (int i = 0; i < 4; i++) {
        ll[i] += __shfl_xor_sync(0xffffffffu, ll[i], 1);
        ll[i] += __shfl_xor_sync(0xffffffffu, ll[i], 2);
    }
    __syncthreads();
    if (tig == 0) {
        #pragma unroll
        for (int mt = 0; mt < 2; mt++)
            #pragma unroll
            for (int rh = 0; rh < 2; rh++)
                ssum[ng * 128 + mi * 32 + mt * 16 + rh * 8 + gid] = ll[mt * 2 + rh];
    }
    __syncthreads();

    #pragma unroll
    for (int mt = 0; mt < 2; mt++) {
        #pragma unroll
        for (int rh = 0; rh < 2; rh++) {
            int row = mi * 32 + mt * 16 + rh * 8 + gid;
            float l = ssum[row] + ssum[128 + row] + ssum[256 + row] + ssum[384 + row];
            float inv = 1.0f / l;
            float* orow = out + ((size_t)b * SEQ + q0 + row) * DIM + vh * 256 + ng * 64 + 2 * tig;
            #pragma unroll
            for (int j = 0; j < 8; j++) {
                float2 v;
                v.x = O[mt][j][rh * 2]     * inv;
                v.y = O[mt][j][rh * 2 + 1] * inv;
                *(float2*)(orow + j * 8) = v;
            }
        }
    }
}

extern "C" void kernel_launch(void* const* d_in, const int* in_sizes, int n_in,
                              void* d_out, int out_size) {
    const float* Q = (const float*)d_in[0];
    const float* K = (const float*)d_in[1];
    const float* V = (const float*)d_in[2];
    const int* mask = (const int*)d_in[3];
    float* out = (float*)d_out;

    size_t n4 = (size_t)BATCH * SEQ * DIM / 4;
    prep_q<<<(unsigned)((n4 + 255) / 256), 256>>>(Q);
    scan_mask<<<BATCH, 1024>>>(mask);
    gather_kv<<<dim3(SEQ / 8, BATCH), 256>>>(K, V, mask);

    cudaFuncSetAttribute(attn_v10, cudaFuncAttributeMaxDynamicSharedMemorySize, SMEM_TOTAL);
    dim3 grid(SEQ / BM, BATCH, 2);
    attn_v10<<<grid, 512, SMEM_TOTAL>>>(out);
}